// round 4
// baseline (speedup 1.0000x reference)
#include <cuda_runtime.h>
#include <cuda_bf16.h>
#include <cstdint>

#define NN 8192        // nodes
#define NW 256         // mask words per row (8192/32)
#define DIM 128
#define LDW 136        // padded bf16 row stride (272 B) -> conflict-free ldmatrix

// exp(-ALPHA*k), ALPHA=2
#define F1 0.13533528323661270f
#define F2 0.018315638888734179f
#define F3 0.0024787521766663585f

// ---------------- scratch (static device globals; no allocation) ----------------
__device__ unsigned g_adj[NN * NW];   // 8 MB adjacency bitmask
__device__ unsigned g_P2[NN * NW];    // 8 MB bool(adj^2)
__device__ float    g_ang[NN];
__device__ float    g_s1[NN];
__device__ float    g_enh1[NN];
__device__ float    g_s2[NN];
__device__ float    g_enh2[NN];
__device__ __align__(16) __nv_bfloat16 g_Whi[3][DIM * LDW];  // pre-split W, [n][k] padded
__device__ __align__(16) __nv_bfloat16 g_Wlo[3][DIM * LDW];

// ================= PTX helpers (family-agnostic ISA only) =================
__device__ __forceinline__ uint32_t smem_u32(const void* p) {
    uint32_t a;
    asm("{ .reg .u64 t; cvta.to.shared.u64 t, %1; cvt.u32.u64 %0, t; }" : "=r"(a) : "l"(p));
    return a;
}
__device__ __forceinline__ void ldm_x4(uint32_t* r, uint32_t addr) {
    asm volatile("ldmatrix.sync.aligned.m8n8.x4.shared.b16 {%0,%1,%2,%3}, [%4];"
                 : "=r"(r[0]), "=r"(r[1]), "=r"(r[2]), "=r"(r[3]) : "r"(addr));
}
__device__ __forceinline__ void mma_bf16(float* c, const uint32_t* a, uint32_t b0, uint32_t b1) {
    asm volatile(
        "mma.sync.aligned.m16n8k16.row.col.f32.bf16.bf16.f32 "
        "{%0,%1,%2,%3}, {%4,%5,%6,%7}, {%8,%9}, {%0,%1,%2,%3};"
        : "+f"(c[0]), "+f"(c[1]), "+f"(c[2]), "+f"(c[3])
        : "r"(a[0]), "r"(a[1]), "r"(a[2]), "r"(a[3]), "r"(b0), "r"(b1));
}

// ---------------- prep: zero adj + s1, split W into bf16 hi/lo [n][k] images ----------
__global__ void prep_kernel(const float* __restrict__ W0, const float* __restrict__ W1,
                            const float* __restrict__ W2) {
    int i = blockIdx.x * blockDim.x + threadIdx.x;
    int stride = gridDim.x * blockDim.x;
    for (int k = i; k < NN * NW; k += stride) g_adj[k] = 0u;
    if (i < NN) g_s1[i] = 0.0f;
    if (i < 3 * DIM * DIM) {
        int l = i >> 14;
        int e = i & 16383;
        int k = e >> 7, n = e & 127;
        const float* W = (l == 0) ? W0 : ((l == 1) ? W1 : W2);
        float w = W[e];  // W[k][n]
        __nv_bfloat16 hi = __float2bfloat16(w);
        __nv_bfloat16 lo = __float2bfloat16(w - __bfloat162float(hi));
        g_Whi[l][n * LDW + k] = hi;   // B operand stored [n][k]
        g_Wlo[l][n * LDW + k] = lo;
    }
}

__global__ void build_adj(const int* __restrict__ ei, int E) {
    int t = blockIdx.x * blockDim.x + threadIdx.x;
    if (t >= E) return;
    int r = ei[t];
    int c = ei[E + t];
    atomicOr(&g_adj[r * NW + (c >> 5)], 1u << (c & 31));
}

// ---------------- fused MLP: 3x (128x128 GEMM + relu) + W3 matvec ----------------
// CTA = 64 rows, 512 threads (16 warps: wm = w&3 -> 16-row tile, wn = w>>2 -> 32-col strip)
#define ROWS_CTA 64
#define SM_W3   0                         // 128 f32
#define SM_ROWS 512                       // 64 f32 row accumulators
#define SM_AHI  768
#define SM_ALO  (SM_AHI + ROWS_CTA * LDW * 2)
#define SM_WHI  (SM_ALO + ROWS_CTA * LDW * 2)
#define SM_WLO  (SM_WHI + DIM * LDW * 2)
#define SM_MLP  (SM_WLO + DIM * LDW * 2)          // ~105 KB

__device__ __forceinline__ void store_split_u32(char* smem, int base, int row, int col,
                                                float x0, float x1) {
    __nv_bfloat16 h0 = __float2bfloat16(x0);
    __nv_bfloat16 h1 = __float2bfloat16(x1);
    *(uint32_t*)(smem + base + (row * LDW + col) * 2) =
        ((uint32_t)__bfloat16_as_ushort(h1) << 16) | (uint32_t)__bfloat16_as_ushort(h0);
}

__device__ __forceinline__ void copy_w_layer(char* smem, int l) {
    const uint4* sh = (const uint4*)g_Whi[l];
    const uint4* sl = (const uint4*)g_Wlo[l];
    uint4* dh = (uint4*)(smem + SM_WHI);
    uint4* dl = (uint4*)(smem + SM_WLO);
#pragma unroll 2
    for (int i = threadIdx.x; i < DIM * LDW * 2 / 16; i += 512) { dh[i] = sh[i]; dl[i] = sl[i]; }
}

__global__ void __launch_bounds__(512, 1)
mlp_kernel(const float* __restrict__ coeffs, const float* __restrict__ W3) {
    extern __shared__ char smem[];
    uint32_t sb = smem_u32(smem);
    int t = threadIdx.x;
    int w = t >> 5, lane = t & 31;
    int wm = w & 3, wn = w >> 2;      // wm: 16-row tile, wn: 32-col strip (0..3)
    int row0 = blockIdx.x * ROWS_CTA;

    if (t < 128) ((float*)(smem + SM_W3))[t] = W3[t];
    if (t < ROWS_CTA) ((float*)(smem + SM_ROWS))[t] = 0.0f;

    // load + split this CTA's A tile: thread t -> row t/8, k-section (t&7)*16
    {
        int r = t >> 3, k0 = (t & 7) * 16;
        const float4* src = (const float4*)(coeffs + (size_t)(row0 + r) * DIM + k0);
#pragma unroll
        for (int i = 0; i < 4; i++) {
            float4 v = src[i];
            int c = k0 + i * 4;
            __nv_bfloat16 h0 = __float2bfloat16(v.x), h1 = __float2bfloat16(v.y);
            __nv_bfloat16 h2 = __float2bfloat16(v.z), h3 = __float2bfloat16(v.w);
            store_split_u32(smem, SM_AHI, r, c,     v.x, v.y);
            store_split_u32(smem, SM_AHI, r, c + 2, v.z, v.w);
            store_split_u32(smem, SM_ALO, r, c,
                            v.x - __bfloat162float(h0), v.y - __bfloat162float(h1));
            store_split_u32(smem, SM_ALO, r, c + 2,
                            v.z - __bfloat162float(h2), v.w - __bfloat162float(h3));
        }
    }
    copy_w_layer(smem, 0);
    __syncthreads();

    const float* W3s = (const float*)(smem + SM_W3);
    float* rows = (float*)(smem + SM_ROWS);
    int rowA = wm * 16;
    int nbase0 = wn * 32;

    for (int layer = 0; layer < 3; layer++) {
        float acc[4][4];
#pragma unroll
        for (int nt = 0; nt < 4; nt++)
#pragma unroll
            for (int q = 0; q < 4; q++) acc[nt][q] = 0.0f;

#pragma unroll 2
        for (int k = 0; k < 8; k++) {
            uint32_t ahi[4], alo[4];
            uint32_t aoff = ((rowA + (lane & 15)) * LDW + k * 16 + ((lane >> 4) * 8)) * 2;
            ldm_x4(ahi, sb + SM_AHI + aoff);
            ldm_x4(alo, sb + SM_ALO + aoff);
#pragma unroll
            for (int np = 0; np < 2; np++) {       // two 16-col pairs
                int nbase = nbase0 + np * 16;
                uint32_t boff = ((nbase + ((lane >> 3) & 1) * 8 + (lane & 7)) * LDW
                                 + k * 16 + ((lane >> 4) * 8)) * 2;
                uint32_t bhi[4], blo[4];
                ldm_x4(bhi, sb + SM_WHI + boff);
                ldm_x4(blo, sb + SM_WLO + boff);
                mma_bf16(acc[np * 2],     ahi, bhi[0], bhi[2]);
                mma_bf16(acc[np * 2],     ahi, blo[0], blo[2]);
                mma_bf16(acc[np * 2],     alo, bhi[0], bhi[2]);
                mma_bf16(acc[np * 2 + 1], ahi, bhi[1], bhi[3]);
                mma_bf16(acc[np * 2 + 1], ahi, blo[1], blo[3]);
                mma_bf16(acc[np * 2 + 1], alo, bhi[1], bhi[3]);
            }
        }
        __syncthreads();   // everyone done reading A (and W) for this layer

        if (layer < 2) {
            int rw = rowA + (lane >> 2);
#pragma unroll
            for (int nt = 0; nt < 4; nt++) {
                int col = nbase0 + nt * 8 + (lane & 3) * 2;
                float f0 = fmaxf(acc[nt][0], 0.0f), f1 = fmaxf(acc[nt][1], 0.0f);
                float f2 = fmaxf(acc[nt][2], 0.0f), f3 = fmaxf(acc[nt][3], 0.0f);
                __nv_bfloat16 h0 = __float2bfloat16(f0), h1 = __float2bfloat16(f1);
                __nv_bfloat16 h2 = __float2bfloat16(f2), h3 = __float2bfloat16(f3);
                store_split_u32(smem, SM_AHI, rw,     col, f0, f1);
                store_split_u32(smem, SM_AHI, rw + 8, col, f2, f3);
                store_split_u32(smem, SM_ALO, rw,     col,
                                f0 - __bfloat162float(h0), f1 - __bfloat162float(h1));
                store_split_u32(smem, SM_ALO, rw + 8, col,
                                f2 - __bfloat162float(h2), f3 - __bfloat162float(h3));
            }
            copy_w_layer(smem, layer + 1);
            __syncthreads();
        } else {
            float p0 = 0.0f, p1 = 0.0f;
#pragma unroll
            for (int nt = 0; nt < 4; nt++) {
                int col = nbase0 + nt * 8 + (lane & 3) * 2;
                p0 += fmaxf(acc[nt][0], 0.0f) * W3s[col] + fmaxf(acc[nt][1], 0.0f) * W3s[col + 1];
                p1 += fmaxf(acc[nt][2], 0.0f) * W3s[col] + fmaxf(acc[nt][3], 0.0f) * W3s[col + 1];
            }
            p0 += __shfl_xor_sync(0xffffffffu, p0, 1);
            p0 += __shfl_xor_sync(0xffffffffu, p0, 2);
            p1 += __shfl_xor_sync(0xffffffffu, p1, 1);
            p1 += __shfl_xor_sync(0xffffffffu, p1, 2);
            if ((lane & 3) == 0) {
                atomicAdd(&rows[rowA + (lane >> 2)], p0);
                atomicAdd(&rows[rowA + (lane >> 2) + 8], p1);
            }
            __syncthreads();
            if (t < ROWS_CTA) g_ang[row0 + t] = rows[t];
        }
    }
}

// ---------------- hop-1 scatter over raw edge list (duplicates counted) ----------------
__global__ void scatter1(const int* __restrict__ ei, int E) {
    int t = blockIdx.x * blockDim.x + threadIdx.x;
    if (t >= E) return;
    atomicAdd(&g_s1[ei[t]], F1 * g_ang[ei[E + t]]);
}

__global__ void enh1_kernel() {
    int i = blockIdx.x * blockDim.x + threadIdx.x;
    if (i < NN) g_enh1[i] = g_ang[i] + g_s1[i];
}

// ---------------- k1: build P2 rows + dot(P2row, enh1) ; 32 rows/block, warp/row ------
__global__ void __launch_bounds__(256) k1_p2() {
    __shared__ float v[NN];          // 32 KB: enh1 staged once per block
    __shared__ short nl[8][128];
    __shared__ int   ncnt[8];
    int t = threadIdx.x, lane = t & 31, w = t >> 5;
    for (int i = t; i < NN; i += 256) v[i] = g_enh1[i];
    __syncthreads();

    for (int rr = 0; rr < 4; rr++) {
        int row = blockIdx.x * 32 + w * 4 + rr;
        if (lane == 0) ncnt[w] = 0;
        __syncwarp();
        const uint4* a4 = (const uint4*)(g_adj + row * NW);
        uint4 m0 = a4[lane], m1 = a4[lane + 32];
        {
            unsigned ws[8] = {m0.x, m0.y, m0.z, m0.w, m1.x, m1.y, m1.z, m1.w};
#pragma unroll
            for (int q = 0; q < 8; q++) {
                unsigned x = ws[q];
                int base = (((q < 4 ? lane : lane + 32) * 4) + (q & 3)) * 32;
                while (x) {
                    int b = __ffs((int)x) - 1;
                    x &= (x - 1);
                    int id = atomicAdd(&ncnt[w], 1);
                    if (id < 128) nl[w][id] = (short)(base + b);
                }
            }
        }
        __syncwarp();
        int n = min(ncnt[w], 128);
        uint4 A0 = make_uint4(0u, 0u, 0u, 0u), A1 = make_uint4(0u, 0u, 0u, 0u);
        for (int kk = 0; kk < n; kk++) {
            const uint4* s4 = (const uint4*)(g_adj + (int)nl[w][kk] * NW);
            uint4 x0 = s4[lane], x1 = s4[lane + 32];
            A0.x |= x0.x; A0.y |= x0.y; A0.z |= x0.z; A0.w |= x0.w;
            A1.x |= x1.x; A1.y |= x1.y; A1.z |= x1.z; A1.w |= x1.w;
        }
        ((uint4*)(g_P2 + row * NW))[lane]      = A0;
        ((uint4*)(g_P2 + row * NW))[lane + 32] = A1;

        float s = 0.0f;
        {
            unsigned dw[8] = {A0.x, A0.y, A0.z, A0.w, A1.x, A1.y, A1.z, A1.w};
#pragma unroll
            for (int q = 0; q < 8; q++) {
                unsigned x = dw[q];
                const float* vb = v + (((q < 4 ? lane : lane + 32) * 4) + (q & 3)) * 32;
                while (x) {
                    int b = __ffs((int)x) - 1;
                    x &= (x - 1);
                    s += vb[b];
                }
            }
        }
#pragma unroll
        for (int o = 16; o; o >>= 1) s += __shfl_xor_sync(0xffffffffu, s, o);
        if (lane == 0) {
            float st2 = g_s1[row] + F2 * s;
            g_s2[row]   = st2;
            g_enh2[row] = v[row] + st2;
        }
        __syncwarp();
    }
}

// ---------------- k2: P3 row in registers (adj-gather of P2) + smem-ffs dot -> out ------
__global__ void __launch_bounds__(256) k2_p3(float* __restrict__ out) {
    __shared__ float v[NN];          // 32 KB: enh2 staged once per block
    __shared__ short nl[8][128];
    __shared__ int   ncnt[8];
    int t = threadIdx.x, lane = t & 31, w = t >> 5;
    for (int i = t; i < NN; i += 256) v[i] = g_enh2[i];
    __syncthreads();

    for (int rr = 0; rr < 4; rr++) {
        int row = blockIdx.x * 32 + w * 4 + rr;
        if (lane == 0) ncnt[w] = 0;
        __syncwarp();
        const uint4* a4 = (const uint4*)(g_adj + row * NW);
        uint4 m0 = a4[lane], m1 = a4[lane + 32];
        {
            unsigned ws[8] = {m0.x, m0.y, m0.z, m0.w, m1.x, m1.y, m1.z, m1.w};
#pragma unroll
            for (int q = 0; q < 8; q++) {
                unsigned x = ws[q];
                int base = (((q < 4 ? lane : lane + 32) * 4) + (q & 3)) * 32;
                while (x) {
                    int b = __ffs((int)x) - 1;
                    x &= (x - 1);
                    int id = atomicAdd(&ncnt[w], 1);
                    if (id < 128) nl[w][id] = (short)(base + b);
                }
            }
        }
        __syncwarp();
        int n = min(ncnt[w], 128);
        uint4 A0 = make_uint4(0u, 0u, 0u, 0u), A1 = make_uint4(0u, 0u, 0u, 0u);
        for (int kk = 0; kk < n; kk++) {
            const uint4* s4 = (const uint4*)(g_P2 + (int)nl[w][kk] * NW);
            uint4 x0 = s4[lane], x1 = s4[lane + 32];
            A0.x |= x0.x; A0.y |= x0.y; A0.z |= x0.z; A0.w |= x0.w;
            A1.x |= x1.x; A1.y |= x1.y; A1.z |= x1.z; A1.w |= x1.w;
        }

        float s = 0.0f;
        {
            unsigned dw[8] = {A0.x, A0.y, A0.z, A0.w, A1.x, A1.y, A1.z, A1.w};
#pragma unroll
            for (int q = 0; q < 8; q++) {
                unsigned x = dw[q];
                const float* vb = v + (((q < 4 ? lane : lane + 32) * 4) + (q & 3)) * 32;
                while (x) {
                    int b = __ffs((int)x) - 1;
                    x &= (x - 1);
                    s += vb[b];
                }
            }
        }
#pragma unroll
        for (int o = 16; o; o >>= 1) s += __shfl_xor_sync(0xffffffffu, s, o);
        if (lane == 0) out[row] = v[row] + g_s2[row] + F3 * s;
        __syncwarp();
    }
}

// ---------------- launch ----------------
extern "C" void kernel_launch(void* const* d_in, const int* in_sizes, int n_in,
                              void* d_out, int out_size) {
    const float* coeffs = (const float*)d_in[0];
    const float* W0 = (const float*)d_in[1];
    const float* W1 = (const float*)d_in[2];
    const float* W2 = (const float*)d_in[3];
    const float* W3 = (const float*)d_in[4];
    const int*   ei = (const int*)d_in[5];
    int E = in_sizes[5] / 2;
    float* out = (float*)d_out;

    cudaFuncSetAttribute(mlp_kernel, cudaFuncAttributeMaxDynamicSharedMemorySize, SM_MLP);

    prep_kernel<<<2048, 256>>>(W0, W1, W2);
    build_adj<<<(E + 255) / 256, 256>>>(ei, E);
    mlp_kernel<<<NN / ROWS_CTA, 512, SM_MLP>>>(coeffs, W3);
    scatter1<<<(E + 255) / 256, 256>>>(ei, E);
    enh1_kernel<<<32, 256>>>();
    k1_p2<<<NN / 32, 256>>>();
    k2_p3<<<NN / 32, 256>>>(out);
}

// round 6
// speedup vs baseline: 1.3113x; 1.3113x over previous
#include <cuda_runtime.h>
#include <cuda_bf16.h>
#include <cstdint>

#define NN 8192        // nodes
#define NW 256         // mask words per row (8192/32)
#define DIM 128
#define LDW 136        // padded bf16 row stride (272 B) -> conflict-free ldmatrix

// exp(-ALPHA*k), ALPHA=2
#define F1 0.13533528323661270f
#define F2 0.018315638888734179f
#define F3 0.0024787521766663585f

// ---------------- scratch (static device globals; no allocation) ----------------
__device__ unsigned g_adj[NN * NW];   // 8 MB adjacency bitmask
__device__ unsigned g_P2[NN * NW];    // 8 MB bool(adj^2)
__device__ float    g_ang[NN];
__device__ float    g_s1[NN];
__device__ float    g_s2[NN];
__device__ float    g_enh2[NN];
__device__ __align__(16) __nv_bfloat16 g_Whi[3][DIM * LDW];  // pre-split W, [n][k] padded
__device__ __align__(16) __nv_bfloat16 g_Wlo[3][DIM * LDW];

// ================= PTX helpers (family-agnostic ISA only) =================
__device__ __forceinline__ uint32_t smem_u32(const void* p) {
    uint32_t a;
    asm("{ .reg .u64 t; cvta.to.shared.u64 t, %1; cvt.u32.u64 %0, t; }" : "=r"(a) : "l"(p));
    return a;
}
__device__ __forceinline__ void ldm_x4(uint32_t* r, uint32_t addr) {
    asm volatile("ldmatrix.sync.aligned.m8n8.x4.shared.b16 {%0,%1,%2,%3}, [%4];"
                 : "=r"(r[0]), "=r"(r[1]), "=r"(r[2]), "=r"(r[3]) : "r"(addr));
}
__device__ __forceinline__ void mma_bf16(float* c, const uint32_t* a, uint32_t b0, uint32_t b1) {
    asm volatile(
        "mma.sync.aligned.m16n8k16.row.col.f32.bf16.bf16.f32 "
        "{%0,%1,%2,%3}, {%4,%5,%6,%7}, {%8,%9}, {%0,%1,%2,%3};"
        : "+f"(c[0]), "+f"(c[1]), "+f"(c[2]), "+f"(c[3])
        : "r"(a[0]), "r"(a[1]), "r"(a[2]), "r"(a[3]), "r"(b0), "r"(b1));
}

// ---------------- prep: zero adj + s1, split W into bf16 hi/lo [n][k] images ----------
__global__ void prep_kernel(const float* __restrict__ W0, const float* __restrict__ W1,
                            const float* __restrict__ W2) {
    int i = blockIdx.x * blockDim.x + threadIdx.x;
    int stride = gridDim.x * blockDim.x;
    for (int k = i; k < NN * NW; k += stride) g_adj[k] = 0u;
    if (i < NN) g_s1[i] = 0.0f;
    if (i < 3 * DIM * DIM) {
        int l = i >> 14;
        int e = i & 16383;
        int k = e >> 7, n = e & 127;
        const float* W = (l == 0) ? W0 : ((l == 1) ? W1 : W2);
        float w = W[e];  // W[k][n]
        __nv_bfloat16 hi = __float2bfloat16(w);
        __nv_bfloat16 lo = __float2bfloat16(w - __bfloat162float(hi));
        g_Whi[l][n * LDW + k] = hi;   // B operand stored [n][k]
        g_Wlo[l][n * LDW + k] = lo;
    }
}

__global__ void build_adj(const int* __restrict__ ei, int E) {
    int t = blockIdx.x * blockDim.x + threadIdx.x;
    if (t >= E) return;
    int r = ei[t];
    int c = ei[E + t];
    atomicOr(&g_adj[r * NW + (c >> 5)], 1u << (c & 31));
}

// ---------------- fused MLP: 3x (128x128 GEMM + relu) + W3 matvec ----------------
// CTA = 64 rows, 512 threads (16 warps: wm = w&3 -> 16-row tile, wn = w>>2 -> 32-col strip)
#define ROWS_CTA 64
#define SM_W3   0                         // 128 f32
#define SM_ROWS 512                       // 64 f32 row accumulators
#define SM_AHI  768
#define SM_ALO  (SM_AHI + ROWS_CTA * LDW * 2)
#define SM_WHI  (SM_ALO + ROWS_CTA * LDW * 2)
#define SM_WLO  (SM_WHI + DIM * LDW * 2)
#define SM_MLP  (SM_WLO + DIM * LDW * 2)          // ~105 KB

__device__ __forceinline__ void store_split_u32(char* smem, int base, int row, int col,
                                                float x0, float x1) {
    __nv_bfloat16 h0 = __float2bfloat16(x0);
    __nv_bfloat16 h1 = __float2bfloat16(x1);
    *(uint32_t*)(smem + base + (row * LDW + col) * 2) =
        ((uint32_t)__bfloat16_as_ushort(h1) << 16) | (uint32_t)__bfloat16_as_ushort(h0);
}

__device__ __forceinline__ void copy_w_layer(char* smem, int l) {
    const uint4* sh = (const uint4*)g_Whi[l];
    const uint4* sl = (const uint4*)g_Wlo[l];
    uint4* dh = (uint4*)(smem + SM_WHI);
    uint4* dl = (uint4*)(smem + SM_WLO);
#pragma unroll 2
    for (int i = threadIdx.x; i < DIM * LDW * 2 / 16; i += 512) { dh[i] = sh[i]; dl[i] = sl[i]; }
}

__global__ void __launch_bounds__(512, 1)
mlp_kernel(const float* __restrict__ coeffs, const float* __restrict__ W3) {
    extern __shared__ char smem[];
    uint32_t sb = smem_u32(smem);
    int t = threadIdx.x;
    int w = t >> 5, lane = t & 31;
    int wm = w & 3, wn = w >> 2;      // wm: 16-row tile, wn: 32-col strip (0..3)
    int row0 = blockIdx.x * ROWS_CTA;

    if (t < 128) ((float*)(smem + SM_W3))[t] = W3[t];
    if (t < ROWS_CTA) ((float*)(smem + SM_ROWS))[t] = 0.0f;

    // load + split this CTA's A tile: thread t -> row t/8, k-section (t&7)*16
    {
        int r = t >> 3, k0 = (t & 7) * 16;
        const float4* src = (const float4*)(coeffs + (size_t)(row0 + r) * DIM + k0);
#pragma unroll
        for (int i = 0; i < 4; i++) {
            float4 v = src[i];
            int c = k0 + i * 4;
            __nv_bfloat16 h0 = __float2bfloat16(v.x), h1 = __float2bfloat16(v.y);
            __nv_bfloat16 h2 = __float2bfloat16(v.z), h3 = __float2bfloat16(v.w);
            store_split_u32(smem, SM_AHI, r, c,     v.x, v.y);
            store_split_u32(smem, SM_AHI, r, c + 2, v.z, v.w);
            store_split_u32(smem, SM_ALO, r, c,
                            v.x - __bfloat162float(h0), v.y - __bfloat162float(h1));
            store_split_u32(smem, SM_ALO, r, c + 2,
                            v.z - __bfloat162float(h2), v.w - __bfloat162float(h3));
        }
    }
    copy_w_layer(smem, 0);
    __syncthreads();

    const float* W3s = (const float*)(smem + SM_W3);
    float* rows = (float*)(smem + SM_ROWS);
    int rowA = wm * 16;
    int nbase0 = wn * 32;

    for (int layer = 0; layer < 3; layer++) {
        float acc[4][4];
#pragma unroll
        for (int nt = 0; nt < 4; nt++)
#pragma unroll
            for (int q = 0; q < 4; q++) acc[nt][q] = 0.0f;

#pragma unroll 2
        for (int k = 0; k < 8; k++) {
            uint32_t ahi[4], alo[4];
            uint32_t aoff = ((rowA + (lane & 15)) * LDW + k * 16 + ((lane >> 4) * 8)) * 2;
            ldm_x4(ahi, sb + SM_AHI + aoff);
            ldm_x4(alo, sb + SM_ALO + aoff);
#pragma unroll
            for (int np = 0; np < 2; np++) {       // two 16-col pairs
                int nbase = nbase0 + np * 16;
                uint32_t boff = ((nbase + ((lane >> 3) & 1) * 8 + (lane & 7)) * LDW
                                 + k * 16 + ((lane >> 4) * 8)) * 2;
                uint32_t bhi[4], blo[4];
                ldm_x4(bhi, sb + SM_WHI + boff);
                ldm_x4(blo, sb + SM_WLO + boff);
                mma_bf16(acc[np * 2],     ahi, bhi[0], bhi[2]);
                mma_bf16(acc[np * 2],     ahi, blo[0], blo[2]);
                mma_bf16(acc[np * 2],     alo, bhi[0], bhi[2]);
                mma_bf16(acc[np * 2 + 1], ahi, bhi[1], bhi[3]);
                mma_bf16(acc[np * 2 + 1], ahi, blo[1], blo[3]);
                mma_bf16(acc[np * 2 + 1], alo, bhi[1], bhi[3]);
            }
        }
        __syncthreads();   // everyone done reading A (and W) for this layer

        if (layer < 2) {
            int rw = rowA + (lane >> 2);
#pragma unroll
            for (int nt = 0; nt < 4; nt++) {
                int col = nbase0 + nt * 8 + (lane & 3) * 2;
                float f0 = fmaxf(acc[nt][0], 0.0f), f1 = fmaxf(acc[nt][1], 0.0f);
                float f2 = fmaxf(acc[nt][2], 0.0f), f3 = fmaxf(acc[nt][3], 0.0f);
                __nv_bfloat16 h0 = __float2bfloat16(f0), h1 = __float2bfloat16(f1);
                __nv_bfloat16 h2 = __float2bfloat16(f2), h3 = __float2bfloat16(f3);
                store_split_u32(smem, SM_AHI, rw,     col, f0, f1);
                store_split_u32(smem, SM_AHI, rw + 8, col, f2, f3);
                store_split_u32(smem, SM_ALO, rw,     col,
                                f0 - __bfloat162float(h0), f1 - __bfloat162float(h1));
                store_split_u32(smem, SM_ALO, rw + 8, col,
                                f2 - __bfloat162float(h2), f3 - __bfloat162float(h3));
            }
            copy_w_layer(smem, layer + 1);
            __syncthreads();
        } else {
            float p0 = 0.0f, p1 = 0.0f;
#pragma unroll
            for (int nt = 0; nt < 4; nt++) {
                int col = nbase0 + nt * 8 + (lane & 3) * 2;
                p0 += fmaxf(acc[nt][0], 0.0f) * W3s[col] + fmaxf(acc[nt][1], 0.0f) * W3s[col + 1];
                p1 += fmaxf(acc[nt][2], 0.0f) * W3s[col] + fmaxf(acc[nt][3], 0.0f) * W3s[col + 1];
            }
            p0 += __shfl_xor_sync(0xffffffffu, p0, 1);
            p0 += __shfl_xor_sync(0xffffffffu, p0, 2);
            p1 += __shfl_xor_sync(0xffffffffu, p1, 1);
            p1 += __shfl_xor_sync(0xffffffffu, p1, 2);
            if ((lane & 3) == 0) {
                atomicAdd(&rows[rowA + (lane >> 2)], p0);
                atomicAdd(&rows[rowA + (lane >> 2) + 8], p1);
            }
            __syncthreads();
            if (t < ROWS_CTA) g_ang[row0 + t] = rows[t];
        }
    }
}

// ---------------- hop-1 scatter, vectorized: 4 edges per thread ----------------
__global__ void scatter1(const int* __restrict__ ei, int E) {
    int t = blockIdx.x * blockDim.x + threadIdx.x;
    if (t * 4 >= E) return;
    int4 r = ((const int4*)ei)[t];
    int4 c = ((const int4*)(ei + E))[t];
    atomicAdd(&g_s1[r.x], F1 * __ldg(&g_ang[c.x]));
    atomicAdd(&g_s1[r.y], F1 * __ldg(&g_ang[c.y]));
    atomicAdd(&g_s1[r.z], F1 * __ldg(&g_ang[c.z]));
    atomicAdd(&g_s1[r.w], F1 * __ldg(&g_ang[c.w]));
}

// ---------------- k1: build P2 rows + sparse ffs dot(P2row, enh1) ----------------
// 512 threads = 16 warps, warp per row, 4 passes -> 64 rows/block, grid 128 (1 wave)
__global__ void __launch_bounds__(512) k1_p2() {
    __shared__ float v[NN];          // 32 KB: enh1 = ang + s1, staged per block
    __shared__ short nl[16][128];
    __shared__ int   ncnt[16];
    int t = threadIdx.x, lane = t & 31, w = t >> 5;
    for (int i = t; i < NN; i += 512) v[i] = g_ang[i] + g_s1[i];
    __syncthreads();

    for (int rr = 0; rr < 4; rr++) {
        int row = blockIdx.x * 64 + rr * 16 + w;
        if (lane == 0) ncnt[w] = 0;
        __syncwarp();
        const uint4* a4 = (const uint4*)(g_adj + row * NW);
        uint4 m0 = a4[lane], m1 = a4[lane + 32];
        {
            unsigned ws[8] = {m0.x, m0.y, m0.z, m0.w, m1.x, m1.y, m1.z, m1.w};
#pragma unroll
            for (int q = 0; q < 8; q++) {
                unsigned x = ws[q];
                int base = (((q < 4 ? lane : lane + 32) * 4) + (q & 3)) * 32;
                while (x) {
                    int b = __ffs((int)x) - 1;
                    x &= (x - 1);
                    int id = atomicAdd(&ncnt[w], 1);
                    if (id < 128) nl[w][id] = (short)(base + b);
                }
            }
        }
        __syncwarp();
        int n = min(ncnt[w], 128);
        uint4 A0 = make_uint4(0u, 0u, 0u, 0u), A1 = make_uint4(0u, 0u, 0u, 0u);
        for (int kk = 0; kk < n; kk++) {
            const uint4* s4 = (const uint4*)(g_adj + (int)nl[w][kk] * NW);
            uint4 x0 = s4[lane], x1 = s4[lane + 32];
            A0.x |= x0.x; A0.y |= x0.y; A0.z |= x0.z; A0.w |= x0.w;
            A1.x |= x1.x; A1.y |= x1.y; A1.z |= x1.z; A1.w |= x1.w;
        }
        ((uint4*)(g_P2 + row * NW))[lane]      = A0;
        ((uint4*)(g_P2 + row * NW))[lane + 32] = A1;

        float s = 0.0f;   // sparse dot (P2 ~3% dense): ffs + LDS
        {
            unsigned dw[8] = {A0.x, A0.y, A0.z, A0.w, A1.x, A1.y, A1.z, A1.w};
#pragma unroll
            for (int q = 0; q < 8; q++) {
                unsigned x = dw[q];
                const float* vb = v + (((q < 4 ? lane : lane + 32) * 4) + (q & 3)) * 32;
                while (x) {
                    int b = __ffs((int)x) - 1;
                    x &= (x - 1);
                    s += vb[b];
                }
            }
        }
#pragma unroll
        for (int o = 16; o; o >>= 1) s += __shfl_xor_sync(0xffffffffu, s, o);
        if (lane == 0) {
            float st2 = g_s1[row] + F2 * s;
            g_s2[row]   = st2;
            g_enh2[row] = v[row] + st2;
        }
        __syncwarp();
    }
}

// ---------------- k2: P3 row in registers + NIBBLE-LUT dense dot -> out ----------------
// smem: v[8192] f32 (32KB) + lut16[2048*16] f32 (128KB) + nlist — 1 CTA/SM, 512 thr
#define K2_V    0
#define K2_LUT  NN
#define K2_NL   (NN + 2048 * 16)              // shorts from here
#define K2_SMEM ((NN + 2048 * 16 + 1024 + 64) * 4)

__global__ void __launch_bounds__(512) k2_p3(float* __restrict__ out) {
    extern __shared__ float sm2[];
    float* v   = sm2 + K2_V;
    float* lut = sm2 + K2_LUT;
    short* nl  = (short*)(sm2 + K2_NL);        // [16][128]
    int*  ncnt = (int*)(nl + 16 * 128);
    int t = threadIdx.x, lane = t & 31, w = t >> 5;

    for (int i = t; i < NN; i += 512) v[i] = g_enh2[i];
    __syncthreads();
    // nibble LUT: group g covers v[4g..4g+3]; lut[g*16+n] = sum of selected
    for (int g = t; g < 2048; g += 512) {
        float f0 = v[g * 4], f1 = v[g * 4 + 1], f2 = v[g * 4 + 2], f3 = v[g * 4 + 3];
        float* L = lut + g * 16;
        L[0] = 0.0f;      L[1] = f0;           L[2] = f1;           L[3] = f0 + f1;
        L[4] = f2;        L[5] = f0 + f2;      L[6] = f1 + f2;      L[7] = f0 + f1 + f2;
        float f23 = f2 + f3;
        L[8] = f3;        L[9] = f0 + f3;      L[10] = f1 + f3;     L[11] = f0 + f1 + f3;
        L[12] = f23;      L[13] = f0 + f23;    L[14] = f1 + f23;    L[15] = f0 + f1 + f23;
    }
    __syncthreads();

    for (int rr = 0; rr < 4; rr++) {
        int row = blockIdx.x * 64 + rr * 16 + w;
        if (lane == 0) ncnt[w] = 0;
        __syncwarp();
        const uint4* a4 = (const uint4*)(g_adj + row * NW);
        uint4 m0 = a4[lane], m1 = a4[lane + 32];
        {
            unsigned ws[8] = {m0.x, m0.y, m0.z, m0.w, m1.x, m1.y, m1.z, m1.w};
#pragma unroll
            for (int q = 0; q < 8; q++) {
                unsigned x = ws[q];
                int base = (((q < 4 ? lane : lane + 32) * 4) + (q & 3)) * 32;
                while (x) {
                    int b = __ffs((int)x) - 1;
                    x &= (x - 1);
                    int id = atomicAdd(&ncnt[w], 1);
                    if (id < 128) nl[w * 128 + id] = (short)(base + b);
                }
            }
        }
        __syncwarp();
        int n = min(ncnt[w], 128);
        uint4 A0 = make_uint4(0u, 0u, 0u, 0u), A1 = make_uint4(0u, 0u, 0u, 0u);
        for (int kk = 0; kk < n; kk++) {
            const uint4* s4 = (const uint4*)(g_P2 + (int)nl[w * 128 + kk] * NW);
            uint4 x0 = s4[lane], x1 = s4[lane + 32];
            A0.x |= x0.x; A0.y |= x0.y; A0.z |= x0.z; A0.w |= x0.w;
            A1.x |= x1.x; A1.y |= x1.y; A1.z |= x1.z; A1.w |= x1.w;
        }

        float s = 0.0f;   // dense dot (~40%): nibble-LUT, 8 LDS per word
        {
            unsigned dw[8] = {A0.x, A0.y, A0.z, A0.w, A1.x, A1.y, A1.z, A1.w};
#pragma unroll
            for (int q = 0; q < 8; q++) {
                unsigned x = dw[q];
                int wi = (q < 4 ? lane : lane + 32) * 4 + (q & 3);   // word index
                const float* Lb = lut + wi * 8 * 16;
#pragma unroll
                for (int h = 0; h < 8; h++)
                    s += Lb[h * 16 + ((x >> (4 * h)) & 15u)];
            }
        }
#pragma unroll
        for (int o = 16; o; o >>= 1) s += __shfl_xor_sync(0xffffffffu, s, o);
        if (lane == 0) out[row] = v[row] + g_s2[row] + F3 * s;
        __syncwarp();
    }
}

// ---------------- launch ----------------
extern "C" void kernel_launch(void* const* d_in, const int* in_sizes, int n_in,
                              void* d_out, int out_size) {
    const float* coeffs = (const float*)d_in[0];
    const float* W0 = (const float*)d_in[1];
    const float* W1 = (const float*)d_in[2];
    const float* W2 = (const float*)d_in[3];
    const float* W3 = (const float*)d_in[4];
    const int*   ei = (const int*)d_in[5];
    int E = in_sizes[5] / 2;
    float* out = (float*)d_out;

    cudaFuncSetAttribute(mlp_kernel, cudaFuncAttributeMaxDynamicSharedMemorySize, SM_MLP);
    cudaFuncSetAttribute(k2_p3, cudaFuncAttributeMaxDynamicSharedMemorySize, K2_SMEM);

    prep_kernel<<<2048, 256>>>(W0, W1, W2);
    build_adj<<<(E + 255) / 256, 256>>>(ei, E);
    mlp_kernel<<<NN / ROWS_CTA, 512, SM_MLP>>>(coeffs, W3);
    scatter1<<<(E / 4 + 255) / 256, 256>>>(ei, E);
    k1_p2<<<NN / 64, 512>>>();
    k2_p3<<<NN / 64, 512, K2_SMEM>>>(out);
}

// round 7
// speedup vs baseline: 1.4165x; 1.0802x over previous
#include <cuda_runtime.h>
#include <cuda_bf16.h>
#include <cooperative_groups.h>
#include <cstdint>

namespace cg = cooperative_groups;

#define NN 8192        // nodes
#define NW 256         // mask words per row (8192/32)
#define DIM 128
#define LDW 136        // padded bf16 row stride (272 B) -> conflict-free ldmatrix

// exp(-ALPHA*k), ALPHA=2
#define F1 0.13533528323661270f
#define F2 0.018315638888734179f
#define F3 0.0024787521766663585f

// ---------------- scratch (static device globals; no allocation) ----------------
__device__ unsigned g_adj[NN * NW];   // 8 MB adjacency bitmask
__device__ unsigned g_P2[NN * NW];    // 8 MB bool(adj^2)
__device__ float    g_ang[NN];
__device__ float    g_s1[NN];
__device__ float    g_enh2[NN];
__device__ int      g_ndup;
__device__ int      g_dupr[4096];
__device__ int      g_dupc[4096];
__device__ __align__(16) __nv_bfloat16 g_Whi[3][DIM * LDW];  // pre-split W, [n][k] padded
__device__ __align__(16) __nv_bfloat16 g_Wlo[3][DIM * LDW];

// ================= PTX helpers (family-agnostic ISA only) =================
__device__ __forceinline__ uint32_t smem_u32(const void* p) {
    uint32_t a;
    asm("{ .reg .u64 t; cvta.to.shared.u64 t, %1; cvt.u32.u64 %0, t; }" : "=r"(a) : "l"(p));
    return a;
}
__device__ __forceinline__ void ldm_x4(uint32_t* r, uint32_t addr) {
    asm volatile("ldmatrix.sync.aligned.m8n8.x4.shared.b16 {%0,%1,%2,%3}, [%4];"
                 : "=r"(r[0]), "=r"(r[1]), "=r"(r[2]), "=r"(r[3]) : "r"(addr));
}
__device__ __forceinline__ void mma_bf16(float* c, const uint32_t* a, uint32_t b0, uint32_t b1) {
    asm volatile(
        "mma.sync.aligned.m16n8k16.row.col.f32.bf16.bf16.f32 "
        "{%0,%1,%2,%3}, {%4,%5,%6,%7}, {%8,%9}, {%0,%1,%2,%3};"
        : "+f"(c[0]), "+f"(c[1]), "+f"(c[2]), "+f"(c[3])
        : "r"(a[0]), "r"(a[1]), "r"(a[2]), "r"(a[3]), "r"(b0), "r"(b1));
}

// ---------------- prep: zero adj (vectorized) + dup counter, split W ----------------
__global__ void prep_kernel(const float* __restrict__ W0, const float* __restrict__ W1,
                            const float* __restrict__ W2) {
    int i = blockIdx.x * blockDim.x + threadIdx.x;     // 0..524287
    ((uint4*)g_adj)[i] = make_uint4(0u, 0u, 0u, 0u);   // 524288 uint4 = 8 MB
    if (i == 0) g_ndup = 0;
    if (i < 3 * DIM * DIM) {
        int l = i >> 14;
        int e = i & 16383;
        int k = e >> 7, n = e & 127;
        const float* W = (l == 0) ? W0 : ((l == 1) ? W1 : W2);
        float w = W[e];  // W[k][n]
        __nv_bfloat16 hi = __float2bfloat16(w);
        __nv_bfloat16 lo = __float2bfloat16(w - __bfloat162float(hi));
        g_Whi[l][n * LDW + k] = hi;   // B operand stored [n][k]
        g_Wlo[l][n * LDW + k] = lo;
    }
}

// ---------------- build adjacency; record duplicate edges via atomicOr old value -------
__global__ void build_adj(const int* __restrict__ ei, int E) {
    int t = blockIdx.x * blockDim.x + threadIdx.x;
    if (t >= E) return;
    int r = ei[t];
    int c = ei[E + t];
    unsigned bit = 1u << (c & 31);
    unsigned old = atomicOr(&g_adj[r * NW + (c >> 5)], bit);
    if (old & bit) {
        int id = atomicAdd(&g_ndup, 1);
        if (id < 4096) { g_dupr[id] = r; g_dupc[id] = c; }
    }
}

// ---------------- fused MLP: 3x (128x128 GEMM + relu) + W3 matvec ----------------
#define ROWS_CTA 64
#define SM_W3   0                         // 128 f32
#define SM_ROWS 512                       // 64 f32 row accumulators
#define SM_AHI  768
#define SM_ALO  (SM_AHI + ROWS_CTA * LDW * 2)
#define SM_WHI  (SM_ALO + ROWS_CTA * LDW * 2)
#define SM_WLO  (SM_WHI + DIM * LDW * 2)
#define SM_MLP  (SM_WLO + DIM * LDW * 2)          // ~105 KB

__device__ __forceinline__ void store_split_u32(char* smem, int base, int row, int col,
                                                float x0, float x1) {
    __nv_bfloat16 h0 = __float2bfloat16(x0);
    __nv_bfloat16 h1 = __float2bfloat16(x1);
    *(uint32_t*)(smem + base + (row * LDW + col) * 2) =
        ((uint32_t)__bfloat16_as_ushort(h1) << 16) | (uint32_t)__bfloat16_as_ushort(h0);
}

__device__ __forceinline__ void copy_w_layer(char* smem, int l) {
    const uint4* sh = (const uint4*)g_Whi[l];
    const uint4* sl = (const uint4*)g_Wlo[l];
    uint4* dh = (uint4*)(smem + SM_WHI);
    uint4* dl = (uint4*)(smem + SM_WLO);
#pragma unroll 2
    for (int i = threadIdx.x; i < DIM * LDW * 2 / 16; i += 512) { dh[i] = sh[i]; dl[i] = sl[i]; }
}

__global__ void __launch_bounds__(512, 1)
mlp_kernel(const float* __restrict__ coeffs, const float* __restrict__ W3) {
    extern __shared__ char smem[];
    uint32_t sb = smem_u32(smem);
    int t = threadIdx.x;
    int w = t >> 5, lane = t & 31;
    int wm = w & 3, wn = w >> 2;      // wm: 16-row tile, wn: 32-col strip (0..3)
    int row0 = blockIdx.x * ROWS_CTA;

    if (t < 128) ((float*)(smem + SM_W3))[t] = W3[t];
    if (t < ROWS_CTA) ((float*)(smem + SM_ROWS))[t] = 0.0f;

    {
        int r = t >> 3, k0 = (t & 7) * 16;
        const float4* src = (const float4*)(coeffs + (size_t)(row0 + r) * DIM + k0);
#pragma unroll
        for (int i = 0; i < 4; i++) {
            float4 v = src[i];
            int c = k0 + i * 4;
            __nv_bfloat16 h0 = __float2bfloat16(v.x), h1 = __float2bfloat16(v.y);
            __nv_bfloat16 h2 = __float2bfloat16(v.z), h3 = __float2bfloat16(v.w);
            store_split_u32(smem, SM_AHI, r, c,     v.x, v.y);
            store_split_u32(smem, SM_AHI, r, c + 2, v.z, v.w);
            store_split_u32(smem, SM_ALO, r, c,
                            v.x - __bfloat162float(h0), v.y - __bfloat162float(h1));
            store_split_u32(smem, SM_ALO, r, c + 2,
                            v.z - __bfloat162float(h2), v.w - __bfloat162float(h3));
        }
    }
    copy_w_layer(smem, 0);
    __syncthreads();

    const float* W3s = (const float*)(smem + SM_W3);
    float* rows = (float*)(smem + SM_ROWS);
    int rowA = wm * 16;
    int nbase0 = wn * 32;

    for (int layer = 0; layer < 3; layer++) {
        float acc[4][4];
#pragma unroll
        for (int nt = 0; nt < 4; nt++)
#pragma unroll
            for (int q = 0; q < 4; q++) acc[nt][q] = 0.0f;

#pragma unroll 2
        for (int k = 0; k < 8; k++) {
            uint32_t ahi[4], alo[4];
            uint32_t aoff = ((rowA + (lane & 15)) * LDW + k * 16 + ((lane >> 4) * 8)) * 2;
            ldm_x4(ahi, sb + SM_AHI + aoff);
            ldm_x4(alo, sb + SM_ALO + aoff);
#pragma unroll
            for (int np = 0; np < 2; np++) {
                int nbase = nbase0 + np * 16;
                uint32_t boff = ((nbase + ((lane >> 3) & 1) * 8 + (lane & 7)) * LDW
                                 + k * 16 + ((lane >> 4) * 8)) * 2;
                uint32_t bhi[4], blo[4];
                ldm_x4(bhi, sb + SM_WHI + boff);
                ldm_x4(blo, sb + SM_WLO + boff);
                mma_bf16(acc[np * 2],     ahi, bhi[0], bhi[2]);
                mma_bf16(acc[np * 2],     ahi, blo[0], blo[2]);
                mma_bf16(acc[np * 2],     alo, bhi[0], bhi[2]);
                mma_bf16(acc[np * 2 + 1], ahi, bhi[1], bhi[3]);
                mma_bf16(acc[np * 2 + 1], ahi, blo[1], blo[3]);
                mma_bf16(acc[np * 2 + 1], alo, bhi[1], bhi[3]);
            }
        }
        __syncthreads();

        if (layer < 2) {
            int rw = rowA + (lane >> 2);
#pragma unroll
            for (int nt = 0; nt < 4; nt++) {
                int col = nbase0 + nt * 8 + (lane & 3) * 2;
                float f0 = fmaxf(acc[nt][0], 0.0f), f1 = fmaxf(acc[nt][1], 0.0f);
                float f2 = fmaxf(acc[nt][2], 0.0f), f3 = fmaxf(acc[nt][3], 0.0f);
                __nv_bfloat16 h0 = __float2bfloat16(f0), h1 = __float2bfloat16(f1);
                __nv_bfloat16 h2 = __float2bfloat16(f2), h3 = __float2bfloat16(f3);
                store_split_u32(smem, SM_AHI, rw,     col, f0, f1);
                store_split_u32(smem, SM_AHI, rw + 8, col, f2, f3);
                store_split_u32(smem, SM_ALO, rw,     col,
                                f0 - __bfloat162float(h0), f1 - __bfloat162float(h1));
                store_split_u32(smem, SM_ALO, rw + 8, col,
                                f2 - __bfloat162float(h2), f3 - __bfloat162float(h3));
            }
            copy_w_layer(smem, layer + 1);
            __syncthreads();
        } else {
            float p0 = 0.0f, p1 = 0.0f;
#pragma unroll
            for (int nt = 0; nt < 4; nt++) {
                int col = nbase0 + nt * 8 + (lane & 3) * 2;
                p0 += fmaxf(acc[nt][0], 0.0f) * W3s[col] + fmaxf(acc[nt][1], 0.0f) * W3s[col + 1];
                p1 += fmaxf(acc[nt][2], 0.0f) * W3s[col] + fmaxf(acc[nt][3], 0.0f) * W3s[col + 1];
            }
            p0 += __shfl_xor_sync(0xffffffffu, p0, 1);
            p0 += __shfl_xor_sync(0xffffffffu, p0, 2);
            p1 += __shfl_xor_sync(0xffffffffu, p1, 1);
            p1 += __shfl_xor_sync(0xffffffffu, p1, 2);
            if ((lane & 3) == 0) {
                atomicAdd(&rows[rowA + (lane >> 2)], p0);
                atomicAdd(&rows[rowA + (lane >> 2) + 8], p1);
            }
            __syncthreads();
            if (t < ROWS_CTA) g_ang[row0 + t] = rows[t];
        }
    }
}

// ================= fused hops: s1 gather + hop2 + hop3, cooperative =================
// grid 128 x 512 (1 CTA/SM), 64 rows/block, warp-per-row x 4 passes.
// smem layout (bytes):
#define FH_V    0                              // 8192 f32 vector
#define FH_LUT  32768                          // 2048*16 f32 nibble LUT
#define FH_NL   163840                         // 64*128 shorts (neighbor lists)
#define FH_RS   180224                         // rowsum[64] f32
#define FH_ST2  180480                         // st2[64] f32
#define FH_NCAP 180736                         // ncap[64] int
#define FH_NCNT 180992                         // ncnt[16] int
#define FH_SMEM 181056

__global__ void __launch_bounds__(512, 1) fused_hops(float* __restrict__ out) {
    extern __shared__ char fsm[];
    float* v      = (float*)(fsm + FH_V);
    float* lut    = (float*)(fsm + FH_LUT);
    short* nl     = (short*)(fsm + FH_NL);
    float* rowsum = (float*)(fsm + FH_RS);
    float* st2s   = (float*)(fsm + FH_ST2);
    int*   ncap   = (int*)(fsm + FH_NCAP);
    int*   ncnt   = (int*)(fsm + FH_NCNT);
    cg::grid_group grid = cg::this_grid();

    int t = threadIdx.x, lane = t & 31, w = t >> 5;
    int row0 = blockIdx.x * 64;

    // ---- Phase A: stage ang; build nlists; s1 = F1*sum(ang[nbrs]); P2 rows ----
    for (int i = t; i < NN; i += 512) v[i] = g_ang[i];
    __syncthreads();

    uint4 P20[4], P21[4];
#pragma unroll
    for (int rr = 0; rr < 4; rr++) {
        int rl = rr * 16 + w;
        int row = row0 + rl;
        if (lane == 0) ncnt[w] = 0;
        __syncwarp();
        const uint4* a4 = (const uint4*)(g_adj + row * NW);
        uint4 m0 = a4[lane], m1 = a4[lane + 32];
        {
            unsigned ws[8] = {m0.x, m0.y, m0.z, m0.w, m1.x, m1.y, m1.z, m1.w};
#pragma unroll
            for (int q = 0; q < 8; q++) {
                unsigned x = ws[q];
                int base = (((q < 4 ? lane : lane + 32) * 4) + (q & 3)) * 32;
                while (x) {
                    int b = __ffs((int)x) - 1;
                    x &= (x - 1);
                    int id = atomicAdd(&ncnt[w], 1);
                    if (id < 128) nl[rl * 128 + id] = (short)(base + b);
                }
            }
        }
        __syncwarp();
        int n = min(ncnt[w], 128);
        if (lane == 0) ncap[rl] = n;

        // s1 partial: sum of ang over distinct neighbors
        float sa = 0.0f;
        for (int kk = lane; kk < n; kk += 32) sa += v[nl[rl * 128 + kk]];

        // P2 OR-gather (kept in registers for phase B)
        uint4 A0 = make_uint4(0u, 0u, 0u, 0u), A1 = make_uint4(0u, 0u, 0u, 0u);
        int kk = 0;
        for (; kk + 2 <= n; kk += 2) {
            const uint4* s40 = (const uint4*)(g_adj + (int)nl[rl * 128 + kk] * NW);
            const uint4* s41 = (const uint4*)(g_adj + (int)nl[rl * 128 + kk + 1] * NW);
            uint4 x0 = s40[lane], y0 = s40[lane + 32];
            uint4 x1 = s41[lane], y1 = s41[lane + 32];
            A0.x |= x0.x | x1.x; A0.y |= x0.y | x1.y; A0.z |= x0.z | x1.z; A0.w |= x0.w | x1.w;
            A1.x |= y0.x | y1.x; A1.y |= y0.y | y1.y; A1.z |= y0.z | y1.z; A1.w |= y0.w | y1.w;
        }
        if (kk < n) {
            const uint4* s4 = (const uint4*)(g_adj + (int)nl[rl * 128 + kk] * NW);
            uint4 x0 = s4[lane], y0 = s4[lane + 32];
            A0.x |= x0.x; A0.y |= x0.y; A0.z |= x0.z; A0.w |= x0.w;
            A1.x |= y0.x; A1.y |= y0.y; A1.z |= y0.z; A1.w |= y0.w;
        }
        P20[rr] = A0; P21[rr] = A1;
        ((uint4*)(g_P2 + row * NW))[lane]      = A0;
        ((uint4*)(g_P2 + row * NW))[lane + 32] = A1;

#pragma unroll
        for (int o = 16; o; o >>= 1) sa += __shfl_xor_sync(0xffffffffu, sa, o);
        if (lane == 0) rowsum[rl] = F1 * sa;
    }
    __syncthreads();
    // duplicate-edge corrections (raw edge list counts duplicates in hop 1)
    {
        int nd = g_ndup; if (nd > 4096) nd = 4096;
        for (int d = t; d < nd; d += 512) {
            int r = g_dupr[d];
            if ((r >> 6) == (int)blockIdx.x)
                atomicAdd(&rowsum[r & 63], F1 * v[g_dupc[d]]);
        }
    }
    __syncthreads();
    if (t < 64) g_s1[row0 + t] = rowsum[t];
    grid.sync();

    // ---- Phase B: v = enh1 = ang + s1; hop-2 dot from register-held P2 rows ----
    for (int i = t; i < NN; i += 512) v[i] += g_s1[i];
    __syncthreads();
#pragma unroll
    for (int rr = 0; rr < 4; rr++) {
        int rl = rr * 16 + w;
        int row = row0 + rl;
        float s = 0.0f;   // sparse ffs dot (~3%)
        {
            unsigned dw[8] = {P20[rr].x, P20[rr].y, P20[rr].z, P20[rr].w,
                              P21[rr].x, P21[rr].y, P21[rr].z, P21[rr].w};
#pragma unroll
            for (int q = 0; q < 8; q++) {
                unsigned x = dw[q];
                const float* vb = v + (((q < 4 ? lane : lane + 32) * 4) + (q & 3)) * 32;
                while (x) {
                    int b = __ffs((int)x) - 1;
                    x &= (x - 1);
                    s += vb[b];
                }
            }
        }
#pragma unroll
        for (int o = 16; o; o >>= 1) s += __shfl_xor_sync(0xffffffffu, s, o);
        if (lane == 0) {
            float st2 = g_s1[row] + F2 * s;
            st2s[rl] = st2;
            g_enh2[row] = v[row] + st2;
        }
    }
    grid.sync();

    // ---- Phase C: v = enh2; nibble LUT; P3 in registers; LUT dot -> out ----
    for (int i = t; i < NN; i += 512) v[i] = g_enh2[i];
    __syncthreads();
    for (int g = t; g < 2048; g += 512) {
        float f0 = v[g * 4], f1 = v[g * 4 + 1], f2 = v[g * 4 + 2], f3 = v[g * 4 + 3];
        float* L = lut + g * 16;
        float f01 = f0 + f1, f23 = f2 + f3;
        L[0] = 0.0f;    L[1] = f0;        L[2] = f1;        L[3] = f01;
        L[4] = f2;      L[5] = f0 + f2;   L[6] = f1 + f2;   L[7] = f01 + f2;
        L[8] = f3;      L[9] = f0 + f3;   L[10] = f1 + f3;  L[11] = f01 + f3;
        L[12] = f23;    L[13] = f0 + f23; L[14] = f1 + f23; L[15] = f01 + f23;
    }
    __syncthreads();

#pragma unroll
    for (int rr = 0; rr < 4; rr++) {
        int rl = rr * 16 + w;
        int row = row0 + rl;
        int n = ncap[rl];
        uint4 A0 = make_uint4(0u, 0u, 0u, 0u), A1 = make_uint4(0u, 0u, 0u, 0u);
        int kk = 0;
        for (; kk + 2 <= n; kk += 2) {
            const uint4* s40 = (const uint4*)(g_P2 + (int)nl[rl * 128 + kk] * NW);
            const uint4* s41 = (const uint4*)(g_P2 + (int)nl[rl * 128 + kk + 1] * NW);
            uint4 x0 = s40[lane], y0 = s40[lane + 32];
            uint4 x1 = s41[lane], y1 = s41[lane + 32];
            A0.x |= x0.x | x1.x; A0.y |= x0.y | x1.y; A0.z |= x0.z | x1.z; A0.w |= x0.w | x1.w;
            A1.x |= y0.x | y1.x; A1.y |= y0.y | y1.y; A1.z |= y0.z | y1.z; A1.w |= y0.w | y1.w;
        }
        if (kk < n) {
            const uint4* s4 = (const uint4*)(g_P2 + (int)nl[rl * 128 + kk] * NW);
            uint4 x0 = s4[lane], y0 = s4[lane + 32];
            A0.x |= x0.x; A0.y |= x0.y; A0.z |= x0.z; A0.w |= x0.w;
            A1.x |= y0.x; A1.y |= y0.y; A1.z |= y0.z; A1.w |= y0.w;
        }

        float s = 0.0f;   // dense dot (~40%): nibble LUT, 8 LDS per word
        {
            unsigned dw[8] = {A0.x, A0.y, A0.z, A0.w, A1.x, A1.y, A1.z, A1.w};
#pragma unroll
            for (int q = 0; q < 8; q++) {
                unsigned x = dw[q];
                int wi = (q < 4 ? lane : lane + 32) * 4 + (q & 3);
                const float* Lb = lut + wi * 8 * 16;
#pragma unroll
                for (int h = 0; h < 8; h++)
                    s += Lb[h * 16 + ((x >> (4 * h)) & 15u)];
            }
        }
#pragma unroll
        for (int o = 16; o; o >>= 1) s += __shfl_xor_sync(0xffffffffu, s, o);
        if (lane == 0) out[row] = v[row] + st2s[rl] + F3 * s;
    }
}

// ---------------- launch ----------------
extern "C" void kernel_launch(void* const* d_in, const int* in_sizes, int n_in,
                              void* d_out, int out_size) {
    const float* coeffs = (const float*)d_in[0];
    const float* W0 = (const float*)d_in[1];
    const float* W1 = (const float*)d_in[2];
    const float* W2 = (const float*)d_in[3];
    const float* W3 = (const float*)d_in[4];
    const int*   ei = (const int*)d_in[5];
    int E = in_sizes[5] / 2;
    float* out = (float*)d_out;

    cudaFuncSetAttribute(mlp_kernel, cudaFuncAttributeMaxDynamicSharedMemorySize, SM_MLP);
    cudaFuncSetAttribute(fused_hops, cudaFuncAttributeMaxDynamicSharedMemorySize, FH_SMEM);

    prep_kernel<<<2048, 256>>>(W0, W1, W2);
    build_adj<<<(E + 255) / 256, 256>>>(ei, E);
    mlp_kernel<<<NN / ROWS_CTA, 512, SM_MLP>>>(coeffs, W3);

    void* kargs[] = { (void*)&out };
    cudaLaunchCooperativeKernel((void*)fused_hops, dim3(128, 1, 1), dim3(512, 1, 1),
                                kargs, FH_SMEM, (cudaStream_t)0);
}

// round 8
// speedup vs baseline: 1.5041x; 1.0618x over previous
#include <cuda_runtime.h>
#include <cuda_bf16.h>
#include <cooperative_groups.h>
#include <cstdint>

namespace cg = cooperative_groups;

#define NN 8192        // nodes
#define NW 256         // mask words per row (8192/32)
#define DIM 128
#define LDW 136        // padded bf16 row stride (272 B) -> conflict-free ldmatrix

// exp(-ALPHA*k), ALPHA=2
#define F1 0.13533528323661270f
#define F2 0.018315638888734179f
#define F3 0.0024787521766663585f

// ---------------- scratch (static device globals; no allocation) ----------------
__device__ unsigned g_adj[NN * NW];   // 8 MB adjacency bitmask
__device__ unsigned g_P2[NN * NW];    // 8 MB bool(adj^2)
__device__ float    g_ang[NN];
__device__ float    g_s1[NN];
__device__ float    g_enh2[NN];
__device__ int      g_ndup;
__device__ int      g_dupr[4096];
__device__ int      g_dupc[4096];
__device__ __align__(16) __nv_bfloat16 g_Whi[3][DIM * LDW];  // pre-split W, [n][k] padded
__device__ __align__(16) __nv_bfloat16 g_Wlo[3][DIM * LDW];

// ================= PTX helpers (family-agnostic ISA only) =================
__device__ __forceinline__ uint32_t smem_u32(const void* p) {
    uint32_t a;
    asm("{ .reg .u64 t; cvta.to.shared.u64 t, %1; cvt.u32.u64 %0, t; }" : "=r"(a) : "l"(p));
    return a;
}
__device__ __forceinline__ void ldm_x4(uint32_t* r, uint32_t addr) {
    asm volatile("ldmatrix.sync.aligned.m8n8.x4.shared.b16 {%0,%1,%2,%3}, [%4];"
                 : "=r"(r[0]), "=r"(r[1]), "=r"(r[2]), "=r"(r[3]) : "r"(addr));
}
__device__ __forceinline__ void mma_bf16(float* c, const uint32_t* a, uint32_t b0, uint32_t b1) {
    asm volatile(
        "mma.sync.aligned.m16n8k16.row.col.f32.bf16.bf16.f32 "
        "{%0,%1,%2,%3}, {%4,%5,%6,%7}, {%8,%9}, {%0,%1,%2,%3};"
        : "+f"(c[0]), "+f"(c[1]), "+f"(c[2]), "+f"(c[3])
        : "r"(a[0]), "r"(a[1]), "r"(a[2]), "r"(a[3]), "r"(b0), "r"(b1));
}

// ---------------- prep: zero adj (vectorized) + dup counter, split W ----------------
__global__ void prep_kernel(const float* __restrict__ W0, const float* __restrict__ W1,
                            const float* __restrict__ W2) {
    int i = blockIdx.x * blockDim.x + threadIdx.x;     // 0..524287
    ((uint4*)g_adj)[i] = make_uint4(0u, 0u, 0u, 0u);   // 524288 uint4 = 8 MB
    if (i == 0) g_ndup = 0;
    if (i < 3 * DIM * DIM) {
        int l = i >> 14;
        int e = i & 16383;
        int k = e >> 7, n = e & 127;
        const float* W = (l == 0) ? W0 : ((l == 1) ? W1 : W2);
        float w = W[e];  // W[k][n]
        __nv_bfloat16 hi = __float2bfloat16(w);
        __nv_bfloat16 lo = __float2bfloat16(w - __bfloat162float(hi));
        g_Whi[l][n * LDW + k] = hi;   // B operand stored [n][k]
        g_Wlo[l][n * LDW + k] = lo;
    }
}

// ---------------- build adjacency; record duplicate edges via atomicOr old value -------
__global__ void build_adj(const int* __restrict__ ei, int E) {
    int t = blockIdx.x * blockDim.x + threadIdx.x;
    if (t >= E) return;
    int r = ei[t];
    int c = ei[E + t];
    unsigned bit = 1u << (c & 31);
    unsigned old = atomicOr(&g_adj[r * NW + (c >> 5)], bit);
    if (old & bit) {
        int id = atomicAdd(&g_ndup, 1);
        if (id < 4096) { g_dupr[id] = r; g_dupc[id] = c; }
    }
}

// ---------------- fused MLP: 3x (128x128 GEMM + relu) + W3 matvec ----------------
#define ROWS_CTA 64
#define SM_W3   0                         // 128 f32
#define SM_ROWS 512                       // 64 f32 row accumulators
#define SM_AHI  768
#define SM_ALO  (SM_AHI + ROWS_CTA * LDW * 2)
#define SM_WHI  (SM_ALO + ROWS_CTA * LDW * 2)
#define SM_WLO  (SM_WHI + DIM * LDW * 2)
#define SM_MLP  (SM_WLO + DIM * LDW * 2)          // ~105 KB

__device__ __forceinline__ void store_split_u32(char* smem, int base, int row, int col,
                                                float x0, float x1) {
    __nv_bfloat16 h0 = __float2bfloat16(x0);
    __nv_bfloat16 h1 = __float2bfloat16(x1);
    *(uint32_t*)(smem + base + (row * LDW + col) * 2) =
        ((uint32_t)__bfloat16_as_ushort(h1) << 16) | (uint32_t)__bfloat16_as_ushort(h0);
}

__device__ __forceinline__ void copy_w_layer(char* smem, int l) {
    const uint4* sh = (const uint4*)g_Whi[l];
    const uint4* sl = (const uint4*)g_Wlo[l];
    uint4* dh = (uint4*)(smem + SM_WHI);
    uint4* dl = (uint4*)(smem + SM_WLO);
#pragma unroll 2
    for (int i = threadIdx.x; i < DIM * LDW * 2 / 16; i += 512) { dh[i] = sh[i]; dl[i] = sl[i]; }
}

__global__ void __launch_bounds__(512, 1)
mlp_kernel(const float* __restrict__ coeffs, const float* __restrict__ W3) {
    extern __shared__ char smem[];
    uint32_t sb = smem_u32(smem);
    int t = threadIdx.x;
    int w = t >> 5, lane = t & 31;
    int wm = w & 3, wn = w >> 2;      // wm: 16-row tile, wn: 32-col strip (0..3)
    int row0 = blockIdx.x * ROWS_CTA;

    if (t < 128) ((float*)(smem + SM_W3))[t] = W3[t];
    if (t < ROWS_CTA) ((float*)(smem + SM_ROWS))[t] = 0.0f;

    {
        int r = t >> 3, k0 = (t & 7) * 16;
        const float4* src = (const float4*)(coeffs + (size_t)(row0 + r) * DIM + k0);
#pragma unroll
        for (int i = 0; i < 4; i++) {
            float4 v = src[i];
            int c = k0 + i * 4;
            __nv_bfloat16 h0 = __float2bfloat16(v.x), h1 = __float2bfloat16(v.y);
            __nv_bfloat16 h2 = __float2bfloat16(v.z), h3 = __float2bfloat16(v.w);
            store_split_u32(smem, SM_AHI, r, c,     v.x, v.y);
            store_split_u32(smem, SM_AHI, r, c + 2, v.z, v.w);
            store_split_u32(smem, SM_ALO, r, c,
                            v.x - __bfloat162float(h0), v.y - __bfloat162float(h1));
            store_split_u32(smem, SM_ALO, r, c + 2,
                            v.z - __bfloat162float(h2), v.w - __bfloat162float(h3));
        }
    }
    copy_w_layer(smem, 0);
    __syncthreads();

    const float* W3s = (const float*)(smem + SM_W3);
    float* rows = (float*)(smem + SM_ROWS);
    int rowA = wm * 16;
    int nbase0 = wn * 32;

    for (int layer = 0; layer < 3; layer++) {
        float acc[4][4];
#pragma unroll
        for (int nt = 0; nt < 4; nt++)
#pragma unroll
            for (int q = 0; q < 4; q++) acc[nt][q] = 0.0f;

#pragma unroll 2
        for (int k = 0; k < 8; k++) {
            uint32_t ahi[4], alo[4];
            uint32_t aoff = ((rowA + (lane & 15)) * LDW + k * 16 + ((lane >> 4) * 8)) * 2;
            ldm_x4(ahi, sb + SM_AHI + aoff);
            ldm_x4(alo, sb + SM_ALO + aoff);
#pragma unroll
            for (int np = 0; np < 2; np++) {
                int nbase = nbase0 + np * 16;
                uint32_t boff = ((nbase + ((lane >> 3) & 1) * 8 + (lane & 7)) * LDW
                                 + k * 16 + ((lane >> 4) * 8)) * 2;
                uint32_t bhi[4], blo[4];
                ldm_x4(bhi, sb + SM_WHI + boff);
                ldm_x4(blo, sb + SM_WLO + boff);
                mma_bf16(acc[np * 2],     ahi, bhi[0], bhi[2]);
                mma_bf16(acc[np * 2],     ahi, blo[0], blo[2]);
                mma_bf16(acc[np * 2],     alo, bhi[0], bhi[2]);
                mma_bf16(acc[np * 2 + 1], ahi, bhi[1], bhi[3]);
                mma_bf16(acc[np * 2 + 1], ahi, blo[1], blo[3]);
                mma_bf16(acc[np * 2 + 1], alo, bhi[1], bhi[3]);
            }
        }
        __syncthreads();

        if (layer < 2) {
            int rw = rowA + (lane >> 2);
#pragma unroll
            for (int nt = 0; nt < 4; nt++) {
                int col = nbase0 + nt * 8 + (lane & 3) * 2;
                float f0 = fmaxf(acc[nt][0], 0.0f), f1 = fmaxf(acc[nt][1], 0.0f);
                float f2 = fmaxf(acc[nt][2], 0.0f), f3 = fmaxf(acc[nt][3], 0.0f);
                __nv_bfloat16 h0 = __float2bfloat16(f0), h1 = __float2bfloat16(f1);
                __nv_bfloat16 h2 = __float2bfloat16(f2), h3 = __float2bfloat16(f3);
                store_split_u32(smem, SM_AHI, rw,     col, f0, f1);
                store_split_u32(smem, SM_AHI, rw + 8, col, f2, f3);
                store_split_u32(smem, SM_ALO, rw,     col,
                                f0 - __bfloat162float(h0), f1 - __bfloat162float(h1));
                store_split_u32(smem, SM_ALO, rw + 8, col,
                                f2 - __bfloat162float(h2), f3 - __bfloat162float(h3));
            }
            copy_w_layer(smem, layer + 1);
            __syncthreads();
        } else {
            float p0 = 0.0f, p1 = 0.0f;
#pragma unroll
            for (int nt = 0; nt < 4; nt++) {
                int col = nbase0 + nt * 8 + (lane & 3) * 2;
                p0 += fmaxf(acc[nt][0], 0.0f) * W3s[col] + fmaxf(acc[nt][1], 0.0f) * W3s[col + 1];
                p1 += fmaxf(acc[nt][2], 0.0f) * W3s[col] + fmaxf(acc[nt][3], 0.0f) * W3s[col + 1];
            }
            p0 += __shfl_xor_sync(0xffffffffu, p0, 1);
            p0 += __shfl_xor_sync(0xffffffffu, p0, 2);
            p1 += __shfl_xor_sync(0xffffffffu, p1, 1);
            p1 += __shfl_xor_sync(0xffffffffu, p1, 2);
            if ((lane & 3) == 0) {
                atomicAdd(&rows[rowA + (lane >> 2)], p0);
                atomicAdd(&rows[rowA + (lane >> 2) + 8], p1);
            }
            __syncthreads();
            if (t < ROWS_CTA) g_ang[row0 + t] = rows[t];
        }
    }
}

// ================= fused hops: s1 gather + hop2 + hop3, cooperative =================
// grid 128 x 512 (1 CTA/SM), 64 rows/block, warp-per-row x 4 passes.
#define FH_V    0                              // 8192 f32 vector
#define FH_LUT  32768                          // 2048*16 f32 nibble LUT (bank-swizzled)
#define FH_NL   163840                         // 64*128 shorts (neighbor lists)
#define FH_RS   180224                         // rowsum[64] f32
#define FH_ST2  180480                         // st2[64] f32
#define FH_NCAP 180736                         // ncap[64] int
#define FH_NCNT 180992                         // ncnt[16] int
#define FH_SMEM 181056

// OR-gather of rows listed in nl[0..n) into (A0, A1), unroll x4 for MLP
__device__ __forceinline__ void or_gather(const unsigned* __restrict__ src,
                                          const short* __restrict__ nlr, int n, int lane,
                                          uint4& A0, uint4& A1) {
    A0 = make_uint4(0u, 0u, 0u, 0u);
    A1 = make_uint4(0u, 0u, 0u, 0u);
    int kk = 0;
    for (; kk + 4 <= n; kk += 4) {
        const uint4* s0 = (const uint4*)(src + (int)nlr[kk]     * NW);
        const uint4* s1 = (const uint4*)(src + (int)nlr[kk + 1] * NW);
        const uint4* s2 = (const uint4*)(src + (int)nlr[kk + 2] * NW);
        const uint4* s3 = (const uint4*)(src + (int)nlr[kk + 3] * NW);
        uint4 a0 = s0[lane], b0 = s0[lane + 32];
        uint4 a1 = s1[lane], b1 = s1[lane + 32];
        uint4 a2 = s2[lane], b2 = s2[lane + 32];
        uint4 a3 = s3[lane], b3 = s3[lane + 32];
        A0.x |= a0.x | a1.x | a2.x | a3.x;  A0.y |= a0.y | a1.y | a2.y | a3.y;
        A0.z |= a0.z | a1.z | a2.z | a3.z;  A0.w |= a0.w | a1.w | a2.w | a3.w;
        A1.x |= b0.x | b1.x | b2.x | b3.x;  A1.y |= b0.y | b1.y | b2.y | b3.y;
        A1.z |= b0.z | b1.z | b2.z | b3.z;  A1.w |= b0.w | b1.w | b2.w | b3.w;
    }
    for (; kk < n; kk++) {
        const uint4* s4 = (const uint4*)(src + (int)nlr[kk] * NW);
        uint4 x0 = s4[lane], y0 = s4[lane + 32];
        A0.x |= x0.x; A0.y |= x0.y; A0.z |= x0.z; A0.w |= x0.w;
        A1.x |= y0.x; A1.y |= y0.y; A1.z |= y0.z; A1.w |= y0.w;
    }
}

__global__ void __launch_bounds__(512, 1) fused_hops(float* __restrict__ out) {
    extern __shared__ char fsm[];
    float* v      = (float*)(fsm + FH_V);
    float* lut    = (float*)(fsm + FH_LUT);
    short* nl     = (short*)(fsm + FH_NL);
    float* rowsum = (float*)(fsm + FH_RS);
    float* st2s   = (float*)(fsm + FH_ST2);
    int*   ncap   = (int*)(fsm + FH_NCAP);
    int*   ncnt   = (int*)(fsm + FH_NCNT);
    cg::grid_group grid = cg::this_grid();

    int t = threadIdx.x, lane = t & 31, w = t >> 5;
    int row0 = blockIdx.x * 64;

    // ---- Phase A: stage ang; build nlists; s1 = F1*sum(ang[nbrs]); P2 rows ----
    for (int i = t; i < NN; i += 512) v[i] = g_ang[i];
    __syncthreads();

    uint4 P20[4], P21[4];
#pragma unroll
    for (int rr = 0; rr < 4; rr++) {
        int rl = rr * 16 + w;
        int row = row0 + rl;
        if (lane == 0) ncnt[w] = 0;
        __syncwarp();
        const uint4* a4 = (const uint4*)(g_adj + row * NW);
        uint4 m0 = a4[lane], m1 = a4[lane + 32];
        {
            unsigned ws[8] = {m0.x, m0.y, m0.z, m0.w, m1.x, m1.y, m1.z, m1.w};
#pragma unroll
            for (int q = 0; q < 8; q++) {
                unsigned x = ws[q];
                int base = (((q < 4 ? lane : lane + 32) * 4) + (q & 3)) * 32;
                while (x) {
                    int b = __ffs((int)x) - 1;
                    x &= (x - 1);
                    int id = atomicAdd(&ncnt[w], 1);
                    if (id < 128) nl[rl * 128 + id] = (short)(base + b);
                }
            }
        }
        __syncwarp();
        int n = min(ncnt[w], 128);
        if (lane == 0) ncap[rl] = n;

        // s1 partial: sum of ang over distinct neighbors
        float sa = 0.0f;
        for (int kk = lane; kk < n; kk += 32) sa += v[nl[rl * 128 + kk]];

        or_gather(g_adj, nl + rl * 128, n, lane, P20[rr], P21[rr]);
        ((uint4*)(g_P2 + row * NW))[lane]      = P20[rr];
        ((uint4*)(g_P2 + row * NW))[lane + 32] = P21[rr];

#pragma unroll
        for (int o = 16; o; o >>= 1) sa += __shfl_xor_sync(0xffffffffu, sa, o);
        if (lane == 0) rowsum[rl] = F1 * sa;
    }
    __syncthreads();
    // duplicate-edge corrections (raw edge list counts duplicates in hop 1)
    {
        int nd = g_ndup; if (nd > 4096) nd = 4096;
        for (int d = t; d < nd; d += 512) {
            int r = g_dupr[d];
            if ((r >> 6) == (int)blockIdx.x)
                atomicAdd(&rowsum[r & 63], F1 * v[g_dupc[d]]);
        }
    }
    __syncthreads();
    if (t < 64) g_s1[row0 + t] = rowsum[t];
    grid.sync();

    // ---- Phase B: v = enh1 = ang + s1; hop-2 dot from register-held P2 rows ----
    for (int i = t; i < NN; i += 512) v[i] += g_s1[i];
    __syncthreads();
#pragma unroll
    for (int rr = 0; rr < 4; rr++) {
        int rl = rr * 16 + w;
        int row = row0 + rl;
        float s = 0.0f;   // sparse ffs dot (~3%)
        {
            unsigned dw[8] = {P20[rr].x, P20[rr].y, P20[rr].z, P20[rr].w,
                              P21[rr].x, P21[rr].y, P21[rr].z, P21[rr].w};
#pragma unroll
            for (int q = 0; q < 8; q++) {
                unsigned x = dw[q];
                const float* vb = v + (((q < 4 ? lane : lane + 32) * 4) + (q & 3)) * 32;
                while (x) {
                    int b = __ffs((int)x) - 1;
                    x &= (x - 1);
                    s += vb[b];
                }
            }
        }
#pragma unroll
        for (int o = 16; o; o >>= 1) s += __shfl_xor_sync(0xffffffffu, s, o);
        if (lane == 0) {
            float st2 = g_s1[row] + F2 * s;
            st2s[rl] = st2;
            g_enh2[row] = v[row] + st2;
        }
    }
    grid.sync();

    // ---- Phase C: v = enh2; bank-swizzled nibble LUT; P3 in regs; LUT dot -> out ----
    for (int i = t; i < NN; i += 512) v[i] = g_enh2[i];
    __syncthreads();
    // LUT entry for pattern n of group g stored at lut[g*16 + (n ^ (g&15))]
    for (int g = t; g < 2048; g += 512) {
        float f0 = v[g * 4], f1 = v[g * 4 + 1], f2 = v[g * 4 + 2], f3 = v[g * 4 + 3];
        float* L = lut + g * 16;
        int sw = g & 15;
#pragma unroll
        for (int n = 0; n < 16; n++) {
            float s = 0.0f;
            if (n & 1) s += f0;
            if (n & 2) s += f1;
            if (n & 4) s += f2;
            if (n & 8) s += f3;
            L[n ^ sw] = s;
        }
    }
    __syncthreads();

#pragma unroll
    for (int rr = 0; rr < 4; rr++) {
        int rl = rr * 16 + w;
        int row = row0 + rl;
        int n = ncap[rl];
        uint4 A0, A1;
        or_gather(g_P2, nl + rl * 128, n, lane, A0, A1);

        float s = 0.0f;   // dense dot (~40%): swizzled nibble LUT, 8 LDS per word
        {
            unsigned dw[8] = {A0.x, A0.y, A0.z, A0.w, A1.x, A1.y, A1.z, A1.w};
#pragma unroll
            for (int q = 0; q < 8; q++) {
                unsigned x = dw[q];
                int wi = (q < 4 ? lane : lane + 32) * 4 + (q & 3);
#pragma unroll
                for (int hh = 0; hh < 8; hh++) {
                    int h = (hh + lane) & 7;               // lane-rotated order
                    int g = wi * 8 + h;
                    unsigned nib = (x >> (4 * h)) & 15u;
                    s += lut[g * 16 + (nib ^ (unsigned)(g & 15))];
                }
            }
        }
#pragma unroll
        for (int o = 16; o; o >>= 1) s += __shfl_xor_sync(0xffffffffu, s, o);
        if (lane == 0) out[row] = v[row] + st2s[rl] + F3 * s;
    }
}

// ---------------- launch ----------------
extern "C" void kernel_launch(void* const* d_in, const int* in_sizes, int n_in,
                              void* d_out, int out_size) {
    const float* coeffs = (const float*)d_in[0];
    const float* W0 = (const float*)d_in[1];
    const float* W1 = (const float*)d_in[2];
    const float* W2 = (const float*)d_in[3];
    const float* W3 = (const float*)d_in[4];
    const int*   ei = (const int*)d_in[5];
    int E = in_sizes[5] / 2;
    float* out = (float*)d_out;

    cudaFuncSetAttribute(mlp_kernel, cudaFuncAttributeMaxDynamicSharedMemorySize, SM_MLP);
    cudaFuncSetAttribute(fused_hops, cudaFuncAttributeMaxDynamicSharedMemorySize, FH_SMEM);

    prep_kernel<<<2048, 256>>>(W0, W1, W2);
    build_adj<<<(E + 255) / 256, 256>>>(ei, E);
    mlp_kernel<<<NN / ROWS_CTA, 512, SM_MLP>>>(coeffs, W3);

    void* kargs[] = { (void*)&out };
    cudaLaunchCooperativeKernel((void*)fused_hops, dim3(128, 1, 1), dim3(512, 1, 1),
                                kargs, FH_SMEM, (cudaStream_t)0);
}